// round 7
// baseline (speedup 1.0000x reference)
#include <cuda_runtime.h>
#include <math.h>

#define BATCH 512
#define INDIM 256
#define HIDD  512
#define HID2  256
#define PAT   10

typedef unsigned long long u64;

// -------- scratch (no allocations allowed) --------
__device__ __align__(128) float g_H [BATCH * HIDD];
__device__ __align__(128) float g_H2[BATCH * HID2];
__device__ __align__(128) float g_A [BATCH * HIDD];
__device__ __align__(128) float g_C [BATCH * HIDD];

// ---------- packed f32x2 helpers (sm_103a) ----------
__device__ __forceinline__ u64 pack2(float lo, float hi) {
    u64 r; asm("mov.b64 %0, {%1, %2};" : "=l"(r) : "f"(lo), "f"(hi)); return r;
}
__device__ __forceinline__ void unpack2(u64 v, float& lo, float& hi) {
    asm("mov.b64 {%0, %1}, %2;" : "=f"(lo), "=f"(hi) : "l"(v));
}
__device__ __forceinline__ u64 ffma2(u64 a, u64 b, u64 c) {
    u64 d; asm("fma.rn.f32x2 %0, %1, %2, %3;" : "=l"(d) : "l"(a), "l"(b), "l"(c)); return d;
}
__device__ __forceinline__ u64 add2(u64 a, u64 b) {
    u64 d; asm("add.rn.f32x2 %0, %1, %2;" : "=l"(d) : "l"(a), "l"(b)); return d;
}
__device__ __forceinline__ u64 dup2(float v) { return pack2(v, v); }
__device__ __forceinline__ u64 relu2(u64 v) {
    float lo, hi; unpack2(v, lo, hi);
    return pack2(fmaxf(lo, 0.f), fmaxf(hi, 0.f));
}

// ============================================================
// Split-K2 GEMM: Out[m][n] = sum_k X[m][k]*W[n][k] (+epilogue)
// Tile 64m x 64n, 256 threads = 2 K-groups of 128. Per group:
// 8 m-groups(8 rows) x 16 n-groups(4 cols) threads, 8m x 4n microtile.
// a-operands are m-packed f32x2 pairs straight from smem (no movs),
// b duplicated via 4 movs. 3 LDS.128 + 16 ffma2 per kk (32 FMA).
// K chunks of 16, double-buffered, ONE barrier per chunk.
// smem: per-group Xs[2][16][64] + Wt[2][16][64] = 4096 f; ex aliased.
// mode 0: BN(+b1)+ReLU ; 1: none ; 2: +p0 ; 3: relu(+p0)
// ============================================================
__device__ __forceinline__ void gemm64_sk2(
    const float* __restrict__ X, const float* __restrict__ W,
    float* __restrict__ Out, int N, int Kstr, int m0, int n0, int mode,
    const float* __restrict__ p0, const float* __restrict__ p1,
    const float* __restrict__ p2, const float* __restrict__ p3,
    const float* __restrict__ p4, float* sm)
{
    const int tid = threadIdx.x;
    const int g   = tid >> 7;
    const int t   = tid & 127;

    float* Xs = sm + g * 4096;   // [2][16][64]
    float* Wt = Xs + 2048;       // [2][16][64]
    float* ex = sm;              // aliased combine buffer (post-barrier)

    const int Kh = Kstr >> 1;
    const int kb = g * Kh;

    const int xrow = t & 63;        // loader row (0..63)
    const int xk   = (t >> 6) * 8;  // k offset 0 or 8

    const float* Xg = X + (size_t)(m0 + xrow) * Kstr + kb + xk;
    const float* Wg = W + (size_t)(n0 + xrow) * Kstr + kb + xk;

    const int tmy = t >> 4;      // 0..7  -> m = tmy*8
    const int txn = t & 15;      // 0..15 -> n = txn*4

    u64 acc[4][4];
#pragma unroll
    for (int r = 0; r < 4; r++)
#pragma unroll
        for (int c = 0; c < 4; c++) acc[r][c] = 0ull;

    float4 xa = *(const float4*)(Xg);
    float4 xb = *(const float4*)(Xg + 4);
    float4 wa = *(const float4*)(Wg);
    float4 wb = *(const float4*)(Wg + 4);

    const int NC = Kh >> 4;
#pragma unroll 1
    for (int c = 0; c < NC; ++c) {
        float* Xb = Xs + (c & 1) * 1024;
        float* Wb = Wt + (c & 1) * 1024;
        Xb[(xk + 0) * 64 + xrow] = xa.x; Xb[(xk + 1) * 64 + xrow] = xa.y;
        Xb[(xk + 2) * 64 + xrow] = xa.z; Xb[(xk + 3) * 64 + xrow] = xa.w;
        Xb[(xk + 4) * 64 + xrow] = xb.x; Xb[(xk + 5) * 64 + xrow] = xb.y;
        Xb[(xk + 6) * 64 + xrow] = xb.z; Xb[(xk + 7) * 64 + xrow] = xb.w;
        Wb[(xk + 0) * 64 + xrow] = wa.x; Wb[(xk + 1) * 64 + xrow] = wa.y;
        Wb[(xk + 2) * 64 + xrow] = wa.z; Wb[(xk + 3) * 64 + xrow] = wa.w;
        Wb[(xk + 4) * 64 + xrow] = wb.x; Wb[(xk + 5) * 64 + xrow] = wb.y;
        Wb[(xk + 6) * 64 + xrow] = wb.z; Wb[(xk + 7) * 64 + xrow] = wb.w;
        __syncthreads();

        if (c + 1 < NC) {
            const int ko = (c + 1) * 16;
            xa = *(const float4*)(Xg + ko);
            xb = *(const float4*)(Xg + ko + 4);
            wa = *(const float4*)(Wg + ko);
            wb = *(const float4*)(Wg + ko + 4);
        }

#pragma unroll
        for (int kk = 0; kk < 16; kk++) {
            ulonglong2 a01 = *(const ulonglong2*)&Xb[kk * 64 + tmy * 8];
            ulonglong2 a23 = *(const ulonglong2*)&Xb[kk * 64 + tmy * 8 + 4];
            float4 b = *(const float4*)&Wb[kk * 64 + txn * 4];
            const u64 b0 = dup2(b.x), b1 = dup2(b.y), b2 = dup2(b.z), b3 = dup2(b.w);
            acc[0][0] = ffma2(a01.x, b0, acc[0][0]); acc[0][1] = ffma2(a01.x, b1, acc[0][1]);
            acc[0][2] = ffma2(a01.x, b2, acc[0][2]); acc[0][3] = ffma2(a01.x, b3, acc[0][3]);
            acc[1][0] = ffma2(a01.y, b0, acc[1][0]); acc[1][1] = ffma2(a01.y, b1, acc[1][1]);
            acc[1][2] = ffma2(a01.y, b2, acc[1][2]); acc[1][3] = ffma2(a01.y, b3, acc[1][3]);
            acc[2][0] = ffma2(a23.x, b0, acc[2][0]); acc[2][1] = ffma2(a23.x, b1, acc[2][1]);
            acc[2][2] = ffma2(a23.x, b2, acc[2][2]); acc[2][3] = ffma2(a23.x, b3, acc[2][3]);
            acc[3][0] = ffma2(a23.y, b0, acc[3][0]); acc[3][1] = ffma2(a23.y, b1, acc[3][1]);
            acc[3][2] = ffma2(a23.y, b2, acc[3][2]); acc[3][3] = ffma2(a23.y, b3, acc[3][3]);
        }
    }

    // ---- combine: group1 -> ex (aliased smem), group0 adds ----
    __syncthreads();
    if (g == 1) {
#pragma unroll
        for (int mp = 0; mp < 4; mp++) {
            float lo0, hi0, lo1, hi1, lo2, hi2, lo3, hi3;
            unpack2(acc[mp][0], lo0, hi0); unpack2(acc[mp][1], lo1, hi1);
            unpack2(acc[mp][2], lo2, hi2); unpack2(acc[mp][3], lo3, hi3);
            *(float4*)&ex[t * 32 + mp * 8]     = make_float4(lo0, lo1, lo2, lo3);
            *(float4*)&ex[t * 32 + mp * 8 + 4] = make_float4(hi0, hi1, hi2, hi3);
        }
    }
    __syncthreads();
    if (g == 1) return;

    float va[8][4];
#pragma unroll
    for (int mp = 0; mp < 4; mp++) {
        unpack2(acc[mp][0], va[mp*2][0], va[mp*2+1][0]);
        unpack2(acc[mp][1], va[mp*2][1], va[mp*2+1][1]);
        unpack2(acc[mp][2], va[mp*2][2], va[mp*2+1][2]);
        unpack2(acc[mp][3], va[mp*2][3], va[mp*2+1][3]);
    }
#pragma unroll
    for (int mp = 0; mp < 4; mp++) {
        float4 e0 = *(const float4*)&ex[t * 32 + mp * 8];
        float4 e1 = *(const float4*)&ex[t * 32 + mp * 8 + 4];
        va[mp*2][0]   += e0.x; va[mp*2][1]   += e0.y; va[mp*2][2]   += e0.z; va[mp*2][3]   += e0.w;
        va[mp*2+1][0] += e1.x; va[mp*2+1][1] += e1.y; va[mp*2+1][2] += e1.z; va[mp*2+1][3] += e1.w;
    }

    // ---- epilogue ----
    const int n = n0 + txn * 4;
    float4 q0 = make_float4(0.f,0.f,0.f,0.f), q1 = q0, q2 = q0, q3 = q0, q4 = q0;
    if (mode == 0) {
        q0 = *(const float4*)(p0 + n); q1 = *(const float4*)(p1 + n);
        q2 = *(const float4*)(p2 + n); q3 = *(const float4*)(p3 + n);
        q4 = *(const float4*)(p4 + n);
    } else if (mode == 2 || mode == 3) {
        q0 = *(const float4*)(p0 + n);
    }
    const float* bias = &q0.x;
    const float* gam  = &q1.x;
    const float* bet  = &q2.x;
    const float* mean = &q3.x;
    const float* var  = &q4.x;

#pragma unroll
    for (int r = 0; r < 8; r++) {
        float v[4];
#pragma unroll
        for (int c2 = 0; c2 < 4; c2++) {
            float v2 = va[r][c2];
            if (mode == 0) {
                v2 += bias[c2];
                v2 = gam[c2] * (v2 - mean[c2]) * rsqrtf(var[c2] + 1e-5f) + bet[c2];
                v2 = fmaxf(v2, 0.f);
            } else if (mode == 2) {
                v2 += bias[c2];
            } else if (mode == 3) {
                v2 = fmaxf(v2 + bias[c2], 0.f);
            }
            v[c2] = v2;
        }
        *(float4*)(Out + (size_t)(m0 + tmy * 8 + r) * N + n) =
            make_float4(v[0], v[1], v[2], v[3]);
    }
}

// ============================================================
// Launch 1: three x-projections, grid (8 n, 8 m, 3 weights), 256 thr.
// ============================================================
__global__ __launch_bounds__(256)
void k_proj(const float* __restrict__ x,
            const float* __restrict__ W1, const float* __restrict__ b1,
            const float* __restrict__ gam, const float* __restrict__ bet,
            const float* __restrict__ mean, const float* __restrict__ var,
            const float* __restrict__ Wa, const float* __restrict__ Wb,
            const float* __restrict__ bs1)
{
    __shared__ __align__(16) float sm[8192];
    const int m0 = blockIdx.y * 64;
    const int n0 = blockIdx.x * 64;
    const int z  = blockIdx.z;
    if (z == 0)
        gemm64_sk2(x, W1, g_H, HIDD, INDIM, m0, n0, 0, b1, gam, bet, mean, var, sm);
    else if (z == 1)
        gemm64_sk2(x, Wa, g_A, HIDD, INDIM, m0, n0, 1,
                   nullptr, nullptr, nullptr, nullptr, nullptr, sm);
    else
        gemm64_sk2(x, Wb, g_C, HIDD, INDIM, m0, n0, 2,
                   bs1, nullptr, nullptr, nullptr, nullptr, sm);
}

// ============================================================
// Launch 2: blocks [0,136) = similarity 32x32 tiles (upper tri),
//           blocks [136,168) = H2 = relu(H@W2^T + b2), 64x64 tiles.
// 256 threads. Sim: 4 K-groups of 64 thr (K/4=128 each), 4i x 4j
// microtile with packed f32x2 adds/FMAs; single combine round.
// ============================================================
__global__ __launch_bounds__(256)
void k_simh2(const float* __restrict__ W2, const float* __restrict__ b2,
             const float* __restrict__ ws2, const float* __restrict__ bs2p,
             float* __restrict__ out_sim)
{
    __shared__ __align__(16) float sm[8448];

    if (blockIdx.x >= 136) {
        const int idx = blockIdx.x - 136;        // 0..31
        const int m0 = (idx >> 2) * 64;          // 8 m-tiles
        const int n0 = (idx & 3) * 64;           // 4 n-tiles
        gemm64_sk2(g_H, W2, g_H2, HID2, HIDD, m0, n0, 3,
                   b2, nullptr, nullptr, nullptr, nullptr, sm);
        return;
    }

    // ---- similarity tile ----
    const int tid = threadIdx.x;
    const int g   = tid >> 6;     // K-group 0..3
    const int t   = tid & 63;

    float* As = sm + g * 2080;    // [2][16][32]
    float* Cs = As + 1024;        // [2][16][32]
    float* Ws = As + 2048;        // [2][16]
    float* ex = sm;               // aliased combine (3*1024 floats)

    // decode upper-triangle tile (bi <= bj)
    int rb = blockIdx.x, bi = 0;
    while (rb >= 16 - bi) { rb -= 16 - bi; ++bi; }
    const int bj = bi + rb;
    const int i0 = bi * 32, j0 = bj * 32;

    const int ti = t >> 3;        // 0..7 -> i = ti*4
    const int tj = t & 7;         // 0..7 -> j = tj*4

    const int lrow = t & 31;
    const int lk   = (t >> 5) * 8;   // 0 or 8
    const int kb   = g * 128;

    const float* Ag = g_A + (size_t)(i0 + lrow) * HIDD + kb + lk;
    const float* Cg = g_C + (size_t)(j0 + lrow) * HIDD + kb + lk;
    const float* Wg = ws2 + kb;

    u64 acc[4][2];
#pragma unroll
    for (int r = 0; r < 4; r++) { acc[r][0] = 0ull; acc[r][1] = 0ull; }

    float4 a0 = *(const float4*)(Ag);
    float4 a1 = *(const float4*)(Ag + 4);
    float4 c0 = *(const float4*)(Cg);
    float4 c1 = *(const float4*)(Cg + 4);
    float4 wv = make_float4(0.f, 0.f, 0.f, 0.f);
    if (t < 4) wv = *(const float4*)(Wg + t * 4);

#pragma unroll 1
    for (int c = 0; c < 8; ++c) {            // 8 chunks of 16 k
        const int bo = (c & 1) * 512;
        As[bo + (lk + 0) * 32 + lrow] = a0.x; As[bo + (lk + 1) * 32 + lrow] = a0.y;
        As[bo + (lk + 2) * 32 + lrow] = a0.z; As[bo + (lk + 3) * 32 + lrow] = a0.w;
        As[bo + (lk + 4) * 32 + lrow] = a1.x; As[bo + (lk + 5) * 32 + lrow] = a1.y;
        As[bo + (lk + 6) * 32 + lrow] = a1.z; As[bo + (lk + 7) * 32 + lrow] = a1.w;
        Cs[bo + (lk + 0) * 32 + lrow] = c0.x; Cs[bo + (lk + 1) * 32 + lrow] = c0.y;
        Cs[bo + (lk + 2) * 32 + lrow] = c0.z; Cs[bo + (lk + 3) * 32 + lrow] = c0.w;
        Cs[bo + (lk + 4) * 32 + lrow] = c1.x; Cs[bo + (lk + 5) * 32 + lrow] = c1.y;
        Cs[bo + (lk + 6) * 32 + lrow] = c1.z; Cs[bo + (lk + 7) * 32 + lrow] = c1.w;
        if (t < 4) *(float4*)&Ws[(c & 1) * 16 + t * 4] = wv;
        __syncthreads();

        if (c + 1 < 8) {
            const int ko = (c + 1) * 16;
            a0 = *(const float4*)(Ag + ko);
            a1 = *(const float4*)(Ag + ko + 4);
            c0 = *(const float4*)(Cg + ko);
            c1 = *(const float4*)(Cg + ko + 4);
            if (t < 4) wv = *(const float4*)(Wg + ko + t * 4);
        }

#pragma unroll
        for (int kk = 0; kk < 16; kk++) {
            float4 av = *(const float4*)&As[bo + kk * 32 + ti * 4];
            ulonglong2 cv = *(const ulonglong2*)&Cs[bo + kk * 32 + tj * 4];
            const u64 w2 = dup2(Ws[(c & 1) * 16 + kk]);
            const u64 ad0 = dup2(av.x), ad1 = dup2(av.y);
            const u64 ad2 = dup2(av.z), ad3 = dup2(av.w);
            acc[0][0] = ffma2(relu2(add2(ad0, cv.x)), w2, acc[0][0]);
            acc[0][1] = ffma2(relu2(add2(ad0, cv.y)), w2, acc[0][1]);
            acc[1][0] = ffma2(relu2(add2(ad1, cv.x)), w2, acc[1][0]);
            acc[1][1] = ffma2(relu2(add2(ad1, cv.y)), w2, acc[1][1]);
            acc[2][0] = ffma2(relu2(add2(ad2, cv.x)), w2, acc[2][0]);
            acc[2][1] = ffma2(relu2(add2(ad2, cv.y)), w2, acc[2][1]);
            acc[3][0] = ffma2(relu2(add2(ad3, cv.x)), w2, acc[3][0]);
            acc[3][1] = ffma2(relu2(add2(ad3, cv.y)), w2, acc[3][1]);
        }
    }

    // ---- combine: groups 1..3 -> ex, group0 adds ----
    __syncthreads();
    if (g > 0) {
#pragma unroll
        for (int r = 0; r < 4; r++) {
            float v0, v1, v2, v3;
            unpack2(acc[r][0], v0, v1);
            unpack2(acc[r][1], v2, v3);
            *(float4*)&ex[(g - 1) * 1024 + t * 16 + r * 4] = make_float4(v0, v1, v2, v3);
        }
    }
    __syncthreads();
    if (g > 0) return;

    float va[4][4];
#pragma unroll
    for (int r = 0; r < 4; r++) {
        unpack2(acc[r][0], va[r][0], va[r][1]);
        unpack2(acc[r][1], va[r][2], va[r][3]);
    }
#pragma unroll
    for (int s = 0; s < 3; s++) {
#pragma unroll
        for (int r = 0; r < 4; r++) {
            float4 e = *(const float4*)&ex[s * 1024 + t * 16 + r * 4];
            va[r][0] += e.x; va[r][1] += e.y; va[r][2] += e.z; va[r][3] += e.w;
        }
    }

    const float bs2 = *bs2p;
#pragma unroll
    for (int r = 0; r < 4; r++) {
#pragma unroll
        for (int cc = 0; cc < 4; cc++) {
            const int i = i0 + ti * 4 + r;
            const int j = j0 + tj * 4 + cc;
            if (i < j) {
                const float s = 1.f / (1.f + __expf(-(va[r][cc] + bs2)));
                out_sim[(size_t)i * BATCH + j] = s;
                out_sim[(size_t)j * BATCH + i] = s;
            } else if (i == j) {
                out_sim[(size_t)i * BATCH + j] = 0.f;
            }
        }
    }
}

// ============================================================
// Launch 3: scores + softmax (reads g_H2), one warp per row.
// ============================================================
__global__ __launch_bounds__(128)
void k_scores(const float* __restrict__ W3, const float* __restrict__ b3,
              float* __restrict__ out_probs, float* __restrict__ out_scores)
{
    const int warp = threadIdx.x >> 5;
    const int lane = threadIdx.x & 31;
    const int row  = blockIdx.x * 4 + warp;
    const float* h = g_H2 + (size_t)row * HID2;

    float acc[PAT];
#pragma unroll
    for (int p = 0; p < PAT; p++) acc[p] = 0.f;

    for (int k = lane; k < HID2; k += 32) {
        const float hv = h[k];
#pragma unroll
        for (int p = 0; p < PAT; p++) acc[p] += hv * W3[p * HID2 + k];
    }
#pragma unroll
    for (int p = 0; p < PAT; p++) {
#pragma unroll
        for (int off = 16; off; off >>= 1)
            acc[p] += __shfl_xor_sync(0xFFFFFFFFu, acc[p], off);
    }
    if (lane == 0) {
        float s[PAT], e[PAT];
        float mx = -1e30f;
#pragma unroll
        for (int p = 0; p < PAT; p++) { s[p] = acc[p] + b3[p]; mx = fmaxf(mx, s[p]); }
        float sum = 0.f;
#pragma unroll
        for (int p = 0; p < PAT; p++) { e[p] = __expf(s[p] - mx); sum += e[p]; }
        const float inv = 1.f / sum;
#pragma unroll
        for (int p = 0; p < PAT; p++) {
            out_scores[row * PAT + p] = s[p];
            out_probs [row * PAT + p] = e[p] * inv;
        }
    }
}

// ============================================================
extern "C" void kernel_launch(void* const* d_in, const int* in_sizes, int n_in,
                              void* d_out, int out_size)
{
    const float* x    = (const float*)d_in[0];
    const float* W1   = (const float*)d_in[1];
    const float* b1   = (const float*)d_in[2];
    const float* gam  = (const float*)d_in[3];
    const float* bet  = (const float*)d_in[4];
    const float* mean = (const float*)d_in[5];
    const float* var  = (const float*)d_in[6];
    const float* W2   = (const float*)d_in[7];
    const float* b2   = (const float*)d_in[8];
    const float* W3   = (const float*)d_in[9];
    const float* b3   = (const float*)d_in[10];
    const float* Wa   = (const float*)d_in[11];
    const float* Wb   = (const float*)d_in[12];
    const float* bs1  = (const float*)d_in[13];
    const float* ws2  = (const float*)d_in[14];
    const float* bs2  = (const float*)d_in[15];

    float* out        = (float*)d_out;
    float* out_probs  = out;
    float* out_scores = out + BATCH * PAT;
    float* out_sim    = out + 2 * BATCH * PAT;

    // 1) H, A, C projections (192 CTAs x 256 thr, split-K2, 8x4 microtile)
    k_proj<<<dim3(8, 8, 3), 256>>>(x, W1, b1, gam, bet, mean, var, Wa, Wb, bs1);
    // 2) sim (136 CTAs, split-K4, 4x4 micro) + H2 (32 CTAs), 256 thr
    k_simh2<<<168, 256>>>(W2, b2, ws2, bs2, out_sim);
    // 3) scores + softmax
    k_scores<<<BATCH / 4, 128>>>(W3, b3, out_probs, out_scores);
}